// round 1
// baseline (speedup 1.0000x reference)
#include <cuda_runtime.h>
#include <cstdint>

#define VOCAB  32000
#define EMBED  100
#define HIDDEN 128
#define BATCH  1024
#define SEQ    256
#define RROWS  8

// Scratch (device globals: allocation-free rule)
__device__ float g_P[VOCAB * HIDDEN];        // emb @ W_ih^T + b_ih + b_hh  (16.4 MB, L2-resident)
__device__ float g_hlast[BATCH * HIDDEN];    // final hidden state

// ---------- packed fp32x2 helpers (Blackwell FFMA2) ----------
__device__ __forceinline__ unsigned long long ffma2(unsigned long long a,
                                                    unsigned long long b,
                                                    unsigned long long c) {
    unsigned long long d;
    asm("fma.rn.f32x2 %0, %1, %2, %3;" : "=l"(d) : "l"(a), "l"(b), "l"(c));
    return d;
}
__device__ __forceinline__ float2 unpack2(unsigned long long a) {
    float2 f;
    asm("mov.b64 {%0, %1}, %2;" : "=f"(f.x), "=f"(f.y) : "l"(a));
    return f;
}

// fp32-faithful tanh: 2 MUFU (EX2 via __expf, RCP via __fdividef), no branches.
// e = exp(-2|x|) underflows to 0 for large |x| -> result saturates to +/-1 exactly.
__device__ __forceinline__ float tanh_fast(float x) {
    float ax = fabsf(x);
    float e  = __expf(-2.0f * ax);
    float r  = __fdividef(1.0f - e, 1.0f + e);
    return copysignf(r, x);
}

// ============================================================
// K1: P[v][h] = sum_e emb[v][e] * W_ih[h][e] + b_ih[h] + b_hh[h]
// 500 CTAs x 128 threads, 64 vocab rows per CTA.
// Thread t holds W_ih row t (100 floats) in registers; emb rows staged
// in double-buffered SMEM (8 rows per chunk), broadcast LDS.128 reads.
// ============================================================
__global__ void __launch_bounds__(128) k_embproj(const float* __restrict__ emb,
                                                 const float* __restrict__ W_ih,
                                                 const float* __restrict__ b_ih,
                                                 const float* __restrict__ b_hh) {
    __shared__ float sh_e[2][8 * EMBED];
    const int tid = threadIdx.x;
    const int v0  = blockIdx.x * 64;

    unsigned long long w2[EMBED / 2];
    {
        const ulonglong2* wr = reinterpret_cast<const ulonglong2*>(W_ih + tid * EMBED);
#pragma unroll
        for (int j = 0; j < EMBED / 4; j++) {
            ulonglong2 u = wr[j];
            w2[2 * j] = u.x; w2[2 * j + 1] = u.y;
        }
    }
    const float bias = b_ih[tid] + b_hh[tid];

    {   // stage chunk 0
        const float4* src = reinterpret_cast<const float4*>(emb + (size_t)v0 * EMBED);
        float4* dst = reinterpret_cast<float4*>(sh_e[0]);
        for (int i = tid; i < 8 * EMBED / 4; i += 128) dst[i] = src[i];
    }
    __syncthreads();

    for (int c = 0; c < 8; c++) {
        if (c < 7) {  // prefetch next chunk into other buffer
            const float4* src =
                reinterpret_cast<const float4*>(emb + (size_t)(v0 + 8 * (c + 1)) * EMBED);
            float4* dst = reinterpret_cast<float4*>(sh_e[(c + 1) & 1]);
            for (int i = tid; i < 8 * EMBED / 4; i += 128) dst[i] = src[i];
        }
        const float* eb = sh_e[c & 1];
#pragma unroll
        for (int r = 0; r < 8; r++) {
            unsigned long long acc0 = 0ULL, acc1 = 0ULL;
            const ulonglong2* e2 = reinterpret_cast<const ulonglong2*>(eb + r * EMBED);
#pragma unroll
            for (int j = 0; j < EMBED / 4; j++) {
                ulonglong2 ev = e2[j];
                acc0 = ffma2(w2[2 * j],     ev.x, acc0);
                acc1 = ffma2(w2[2 * j + 1], ev.y, acc1);
            }
            float2 s0 = unpack2(acc0), s1 = unpack2(acc1);
            g_P[(size_t)(v0 + 8 * c + r) * HIDDEN + tid] = s0.x + s0.y + s1.x + s1.y + bias;
        }
        __syncthreads();
    }
}

// ============================================================
// K2: RNN recurrence. 128 CTAs x 128 threads, 8 batch rows per CTA.
// Thread t holds W_hh row t (128 floats = 64 f32x2) in registers.
// h double-buffered in SMEM; xp = gather of g_P rows, prefetched 1 step ahead.
// ============================================================
__global__ void __launch_bounds__(128) k_rnn(const void* __restrict__ x_raw,
                                             const float* __restrict__ W_hh) {
    __shared__ float sh_h[2][RROWS][HIDDEN];
    __shared__ int   sh_x[RROWS * SEQ];
    const int tid = threadIdx.x;
    const int b0  = blockIdx.x * RROWS;

    // --- dtype self-detection: x may be int64 (jax x64 on) or int32 ---
    // If data is int32, reading pairs as int64 yields values >= 2^32 (hi half is a
    // random index, nonzero w.p. ~1-3e-5 each) -> range check over 16 elements.
    const long long* x64 = reinterpret_cast<const long long*>(x_raw);
    const int*       x32 = reinterpret_cast<const int*>(x_raw);
    bool is64 = true;
#pragma unroll
    for (int k = 0; k < 16; k++) {
        long long v = x64[k];
        if (v < 0 || v >= (long long)VOCAB) is64 = false;
    }
    if (is64) {
        for (int i = tid; i < RROWS * SEQ; i += 128)
            sh_x[i] = (int)x64[(size_t)b0 * SEQ + i];
    } else {
        for (int i = tid; i < RROWS * SEQ; i += 128)
            sh_x[i] = x32[(size_t)b0 * SEQ + i];
    }

#pragma unroll
    for (int b = 0; b < RROWS; b++) sh_h[0][b][tid] = 0.0f;

    unsigned long long w2[HIDDEN / 2];
    {
        const ulonglong2* wr = reinterpret_cast<const ulonglong2*>(W_hh + tid * HIDDEN);
#pragma unroll
        for (int j = 0; j < HIDDEN / 4; j++) {
            ulonglong2 u = wr[j];
            w2[2 * j] = u.x; w2[2 * j + 1] = u.y;
        }
    }
    __syncthreads();

    // prefetch xp for t=0
    float g[RROWS];
#pragma unroll
    for (int b = 0; b < RROWS; b++)
        g[b] = g_P[(size_t)sh_x[b * SEQ + 0] * HIDDEN + tid];

    float hn[RROWS];
    for (int t = 0; t < SEQ; t++) {
        const int rb = t & 1;
        unsigned long long acc[RROWS];
#pragma unroll
        for (int b = 0; b < RROWS; b++) acc[b] = 0ULL;

        // matvec: acc_b += W_hh[tid][:] . h_b[:]   (broadcast LDS.128, reg-resident W)
#pragma unroll
        for (int j = 0; j < HIDDEN / 4; j++) {
#pragma unroll
            for (int b = 0; b < RROWS; b++) {
                ulonglong2 hv =
                    *reinterpret_cast<const ulonglong2*>(&sh_h[rb][b][4 * j]);
                acc[b] = ffma2(w2[2 * j],     hv.x, acc[b]);
                acc[b] = ffma2(w2[2 * j + 1], hv.y, acc[b]);
            }
        }

        // prefetch next step's xp gather (hides L2 latency under tanh+sync+next dot)
        float gn[RROWS];
        if (t < SEQ - 1) {
#pragma unroll
            for (int b = 0; b < RROWS; b++)
                gn[b] = g_P[(size_t)sh_x[b * SEQ + (t + 1)] * HIDDEN + tid];
        }

#pragma unroll
        for (int b = 0; b < RROWS; b++) {
            float2 s = unpack2(acc[b]);
            hn[b] = tanh_fast(s.x + s.y + g[b]);
            sh_h[1 - rb][b][tid] = hn[b];
            g[b] = (t < SEQ - 1) ? gn[b] : 0.0f;
        }
        __syncthreads();
    }

#pragma unroll
    for (int b = 0; b < RROWS; b++)
        g_hlast[(size_t)(b0 + b) * HIDDEN + tid] = hn[b];
}

// ============================================================
// K3: out[b][v] = h_last[b] . W_fc[v] + b_fc[v]
// 1000 CTAs (250 vocab tiles x 4 batch quarters) for wave balance.
// Thread t holds W_fc row (v0+t) in 128 registers; h staged in SMEM chunks.
// ============================================================
__global__ void __launch_bounds__(128) k_fc(const float* __restrict__ W_fc,
                                            const float* __restrict__ b_fc,
                                            float* __restrict__ out) {
    __shared__ float sh_h[2][8][HIDDEN];
    const int tid = threadIdx.x;
    const int vt  = blockIdx.x >> 2;
    const int bq  = blockIdx.x & 3;
    const int v   = vt * 128 + tid;
    const int bbase = bq * 256;

    unsigned long long w2[HIDDEN / 2];
    {
        const ulonglong2* wr = reinterpret_cast<const ulonglong2*>(W_fc + (size_t)v * HIDDEN);
#pragma unroll
        for (int j = 0; j < HIDDEN / 4; j++) {
            ulonglong2 u = wr[j];
            w2[2 * j] = u.x; w2[2 * j + 1] = u.y;
        }
    }
    const float bias = b_fc[v];

    {   // stage chunk 0
        const float4* src =
            reinterpret_cast<const float4*>(g_hlast + (size_t)bbase * HIDDEN);
        float4* dst = reinterpret_cast<float4*>(&sh_h[0][0][0]);
        for (int i = tid; i < 8 * HIDDEN / 4; i += 128) dst[i] = src[i];
    }
    __syncthreads();

    for (int c = 0; c < 32; c++) {
        if (c < 31) {
            const float4* src = reinterpret_cast<const float4*>(
                g_hlast + (size_t)(bbase + 8 * (c + 1)) * HIDDEN);
            float4* dst = reinterpret_cast<float4*>(&sh_h[(c + 1) & 1][0][0]);
            for (int i = tid; i < 8 * HIDDEN / 4; i += 128) dst[i] = src[i];
        }
#pragma unroll
        for (int r = 0; r < 8; r++) {
            unsigned long long acc0 = 0ULL, acc1 = 0ULL;
            const ulonglong2* h2 =
                reinterpret_cast<const ulonglong2*>(&sh_h[c & 1][r][0]);
#pragma unroll
            for (int j = 0; j < HIDDEN / 4; j++) {
                ulonglong2 hv = h2[j];
                acc0 = ffma2(w2[2 * j],     hv.x, acc0);
                acc1 = ffma2(w2[2 * j + 1], hv.y, acc1);
            }
            float2 s0 = unpack2(acc0), s1 = unpack2(acc1);
            out[(size_t)(bbase + 8 * c + r) * VOCAB + v] =
                s0.x + s0.y + s1.x + s1.y + bias;
        }
        __syncthreads();
    }
}

// ============================================================
extern "C" void kernel_launch(void* const* d_in, const int* in_sizes, int n_in,
                              void* d_out, int out_size) {
    const void*  x    = d_in[0];                    // int32 or int64 (self-detected)
    const float* emb  = (const float*)d_in[1];      // [32000,100]
    const float* W_ih = (const float*)d_in[2];      // [128,100]
    const float* W_hh = (const float*)d_in[3];      // [128,128]
    const float* b_ih = (const float*)d_in[4];      // [128]
    const float* b_hh = (const float*)d_in[5];      // [128]
    const float* W_fc = (const float*)d_in[6];      // [32000,128]
    const float* b_fc = (const float*)d_in[7];      // [32000]
    float* out = (float*)d_out;                     // [1024,32000]

    k_embproj<<<VOCAB / 64, 128>>>(emb, W_ih, b_ih, b_hh);
    k_rnn<<<BATCH / RROWS, 128>>>(x, W_hh);
    k_fc<<<(VOCAB / 128) * 4, 128>>>(W_fc, b_fc, out);
}

// round 3
// speedup vs baseline: 1.0820x; 1.0820x over previous
#include <cuda_runtime.h>
#include <cstdint>

#define VOCAB  32000
#define EMBED  100
#define HIDDEN 128
#define BATCH  1024
#define SEQ    256
#define RROWS  4   // batch rows per CTA (grid = 256 -> ~2 CTAs/SM -> 2 warps/SMSP)

// Scratch (device globals: allocation-free rule)
__device__ float g_P[VOCAB * HIDDEN];        // emb @ W_ih^T + b_ih + b_hh  (16.4 MB, L2-resident)
__device__ float g_hlast[BATCH * HIDDEN];    // final hidden state

// ---------- packed fp32x2 helpers (Blackwell FFMA2) ----------
__device__ __forceinline__ unsigned long long ffma2(unsigned long long a,
                                                    unsigned long long b,
                                                    unsigned long long c) {
    unsigned long long d;
    asm("fma.rn.f32x2 %0, %1, %2, %3;" : "=l"(d) : "l"(a), "l"(b), "l"(c));
    return d;
}
__device__ __forceinline__ float2 unpack2(unsigned long long a) {
    float2 f;
    asm("mov.b64 {%0, %1}, %2;" : "=f"(f.x), "=f"(f.y) : "l"(a));
    return f;
}

// fp32-faithful tanh: 2 MUFU (EX2 via __expf, RCP via __fdividef), no branches.
__device__ __forceinline__ float tanh_fast(float x) {
    float ax = fabsf(x);
    float e  = __expf(-2.0f * ax);
    float r  = __fdividef(1.0f - e, 1.0f + e);
    return copysignf(r, x);
}

// ============================================================
// K1: P[v][h] = sum_e emb[v][e] * W_ih[h][e] + b_ih[h] + b_hh[h]
// ============================================================
__global__ void __launch_bounds__(128) k_embproj(const float* __restrict__ emb,
                                                 const float* __restrict__ W_ih,
                                                 const float* __restrict__ b_ih,
                                                 const float* __restrict__ b_hh) {
    __shared__ float sh_e[2][8 * EMBED];
    const int tid = threadIdx.x;
    const int v0  = blockIdx.x * 64;

    unsigned long long w2[EMBED / 2];
    {
        const ulonglong2* wr = reinterpret_cast<const ulonglong2*>(W_ih + tid * EMBED);
#pragma unroll
        for (int j = 0; j < EMBED / 4; j++) {
            ulonglong2 u = wr[j];
            w2[2 * j] = u.x; w2[2 * j + 1] = u.y;
        }
    }
    const float bias = b_ih[tid] + b_hh[tid];

    {   // stage chunk 0
        const float4* src = reinterpret_cast<const float4*>(emb + (size_t)v0 * EMBED);
        float4* dst = reinterpret_cast<float4*>(sh_e[0]);
        for (int i = tid; i < 8 * EMBED / 4; i += 128) dst[i] = src[i];
    }
    __syncthreads();

    for (int c = 0; c < 8; c++) {
        if (c < 7) {  // prefetch next chunk into other buffer
            const float4* src =
                reinterpret_cast<const float4*>(emb + (size_t)(v0 + 8 * (c + 1)) * EMBED);
            float4* dst = reinterpret_cast<float4*>(sh_e[(c + 1) & 1]);
            for (int i = tid; i < 8 * EMBED / 4; i += 128) dst[i] = src[i];
        }
        const float* eb = sh_e[c & 1];
#pragma unroll
        for (int r = 0; r < 8; r++) {
            unsigned long long acc0 = 0ULL, acc1 = 0ULL;
            const ulonglong2* e2 = reinterpret_cast<const ulonglong2*>(eb + r * EMBED);
#pragma unroll
            for (int j = 0; j < EMBED / 4; j++) {
                ulonglong2 ev = e2[j];
                acc0 = ffma2(w2[2 * j],     ev.x, acc0);
                acc1 = ffma2(w2[2 * j + 1], ev.y, acc1);
            }
            float2 s0 = unpack2(acc0), s1 = unpack2(acc1);
            g_P[(size_t)(v0 + 8 * c + r) * HIDDEN + tid] = s0.x + s0.y + s1.x + s1.y + bias;
        }
        __syncthreads();
    }
}

// ============================================================
// K2: RNN recurrence. 256 CTAs x 128 threads, 4 batch rows per CTA.
// Thread t holds W_hh row t (128 floats = 64 f32x2) in registers.
// h double-buffered in SMEM; xp = gather of g_P rows, prefetched 1 step ahead.
// 2 CTAs/SM -> 2 warps/SMSP so LDS latency + FFMA2 RAW chains are covered
// by cross-warp issue (round-0 config had 1 warp/SMSP and stalled ~75%).
// ============================================================
__global__ void __launch_bounds__(128, 2) k_rnn(const void* __restrict__ x_raw,
                                                const float* __restrict__ W_hh) {
    __shared__ float sh_h[2][RROWS][HIDDEN];
    __shared__ int   sh_x[RROWS * SEQ];
    const int tid = threadIdx.x;
    const int b0  = blockIdx.x * RROWS;

    // --- dtype self-detection: x may be int64 (jax x64 on) or int32 ---
    const long long* x64 = reinterpret_cast<const long long*>(x_raw);
    const int*       x32 = reinterpret_cast<const int*>(x_raw);
    bool is64 = true;
#pragma unroll
    for (int k = 0; k < 16; k++) {
        long long v = x64[k];
        if (v < 0 || v >= (long long)VOCAB) is64 = false;
    }
    if (is64) {
        for (int i = tid; i < RROWS * SEQ; i += 128)
            sh_x[i] = (int)x64[(size_t)b0 * SEQ + i];
    } else {
        for (int i = tid; i < RROWS * SEQ; i += 128)
            sh_x[i] = x32[(size_t)b0 * SEQ + i];
    }

#pragma unroll
    for (int b = 0; b < RROWS; b++) sh_h[0][b][tid] = 0.0f;

    unsigned long long w2[HIDDEN / 2];
    {
        const ulonglong2* wr = reinterpret_cast<const ulonglong2*>(W_hh + tid * HIDDEN);
#pragma unroll
        for (int j = 0; j < HIDDEN / 4; j++) {
            ulonglong2 u = wr[j];
            w2[2 * j] = u.x; w2[2 * j + 1] = u.y;
        }
    }
    __syncthreads();

    // prefetch xp for t=0
    float g[RROWS];
#pragma unroll
    for (int b = 0; b < RROWS; b++)
        g[b] = g_P[(size_t)sh_x[b * SEQ + 0] * HIDDEN + tid];

    float hn[RROWS];
    for (int t = 0; t < SEQ; t++) {
        const int rb = t & 1;
        unsigned long long acc[RROWS];
#pragma unroll
        for (int b = 0; b < RROWS; b++) acc[b] = 0ULL;

        // matvec: acc_b += W_hh[tid][:] . h_b[:]   (broadcast LDS.128, reg-resident W)
#pragma unroll
        for (int j = 0; j < HIDDEN / 4; j++) {
#pragma unroll
            for (int b = 0; b < RROWS; b++) {
                ulonglong2 hv =
                    *reinterpret_cast<const ulonglong2*>(&sh_h[rb][b][4 * j]);
                acc[b] = ffma2(w2[2 * j],     hv.x, acc[b]);
                acc[b] = ffma2(w2[2 * j + 1], hv.y, acc[b]);
            }
        }

        // prefetch next step's xp gather (hides L2 latency under tanh+sync)
        float gn[RROWS];
        if (t < SEQ - 1) {
#pragma unroll
            for (int b = 0; b < RROWS; b++)
                gn[b] = g_P[(size_t)sh_x[b * SEQ + (t + 1)] * HIDDEN + tid];
        }

#pragma unroll
        for (int b = 0; b < RROWS; b++) {
            float2 s = unpack2(acc[b]);
            hn[b] = tanh_fast(s.x + s.y + g[b]);
            sh_h[1 - rb][b][tid] = hn[b];
            g[b] = (t < SEQ - 1) ? gn[b] : 0.0f;
        }
        __syncthreads();
    }

#pragma unroll
    for (int b = 0; b < RROWS; b++)
        g_hlast[(size_t)(b0 + b) * HIDDEN + tid] = hn[b];
}

// ============================================================
// K3: out[b][v] = h_last[b] . W_fc[v] + b_fc[v]
// 1000 CTAs (250 vocab tiles x 4 batch quarters) for wave balance.
// ============================================================
__global__ void __launch_bounds__(128) k_fc(const float* __restrict__ W_fc,
                                            const float* __restrict__ b_fc,
                                            float* __restrict__ out) {
    __shared__ float sh_h[2][8][HIDDEN];
    const int tid = threadIdx.x;
    const int vt  = blockIdx.x >> 2;
    const int bq  = blockIdx.x & 3;
    const int v   = vt * 128 + tid;
    const int bbase = bq * 256;

    unsigned long long w2[HIDDEN / 2];
    {
        const ulonglong2* wr = reinterpret_cast<const ulonglong2*>(W_fc + (size_t)v * HIDDEN);
#pragma unroll
        for (int j = 0; j < HIDDEN / 4; j++) {
            ulonglong2 u = wr[j];
            w2[2 * j] = u.x; w2[2 * j + 1] = u.y;
        }
    }
    const float bias = b_fc[v];

    {   // stage chunk 0
        const float4* src =
            reinterpret_cast<const float4*>(g_hlast + (size_t)bbase * HIDDEN);
        float4* dst = reinterpret_cast<float4*>(&sh_h[0][0][0]);
        for (int i = tid; i < 8 * HIDDEN / 4; i += 128) dst[i] = src[i];
    }
    __syncthreads();

    for (int c = 0; c < 32; c++) {
        if (c < 31) {
            const float4* src = reinterpret_cast<const float4*>(
                g_hlast + (size_t)(bbase + 8 * (c + 1)) * HIDDEN);
            float4* dst = reinterpret_cast<float4*>(&sh_h[(c + 1) & 1][0][0]);
            for (int i = tid; i < 8 * HIDDEN / 4; i += 128) dst[i] = src[i];
        }
#pragma unroll
        for (int r = 0; r < 8; r++) {
            unsigned long long acc0 = 0ULL, acc1 = 0ULL;
            const ulonglong2* h2 =
                reinterpret_cast<const ulonglong2*>(&sh_h[c & 1][r][0]);
#pragma unroll
            for (int j = 0; j < HIDDEN / 4; j++) {
                ulonglong2 hv = h2[j];
                acc0 = ffma2(w2[2 * j],     hv.x, acc0);
                acc1 = ffma2(w2[2 * j + 1], hv.y, acc1);
            }
            float2 s0 = unpack2(acc0), s1 = unpack2(acc1);
            out[(size_t)(bbase + 8 * c + r) * VOCAB + v] =
                s0.x + s0.y + s1.x + s1.y + bias;
        }
        __syncthreads();
    }
}

// ============================================================
extern "C" void kernel_launch(void* const* d_in, const int* in_sizes, int n_in,
                              void* d_out, int out_size) {
    const void*  x    = d_in[0];                    // int32 or int64 (self-detected)
    const float* emb  = (const float*)d_in[1];      // [32000,100]
    const float* W_ih = (const float*)d_in[2];      // [128,100]
    const float* W_hh = (const float*)d_in[3];      // [128,128]
    const float* b_ih = (const float*)d_in[4];      // [128]
    const float* b_hh = (const float*)d_in[5];      // [128]
    const float* W_fc = (const float*)d_in[6];      // [32000,128]
    const float* b_fc = (const float*)d_in[7];      // [32000]
    float* out = (float*)d_out;                     // [1024,32000]

    k_embproj<<<VOCAB / 64, 128>>>(emb, W_ih, b_ih, b_hh);
    k_rnn<<<BATCH / RROWS, 128>>>(x, W_hh);
    k_fc<<<(VOCAB / 128) * 4, 128>>>(W_fc, b_fc, out);
}